// round 13
// baseline (speedup 1.0000x reference)
#include <cuda_runtime.h>
#include <cstdint>

// Problem constants
#define NBATCH  16
#define NATOM   128
#define TPRIME  16384
#define WS      132     // padded row stride for weight tile in smem
#define HS      132     // padded row stride for H / Hx tiles in smem
#define EPSV    1e-4f

static __device__ __forceinline__ float softplus_eps(float v) {
    // jax.nn.softplus = logaddexp(v, 0) = max(v,0) + log1p(exp(-|v|))
    return fmaxf(v, 0.f) + log1pf(expf(-fabsf(v))) + EPSV;
}

// Load a 128x128 row-major fp32 matrix from gmem into smem [o][WS].
// Coalesced float4 gmem reads; smem float4 stores are conflict-free with WS=132.
__device__ __forceinline__ void load_w128(const float* __restrict__ g,
                                          float* __restrict__ sW, int tid) {
#pragma unroll
    for (int l = 0; l < 16; ++l) {
        int v = l * 256 + tid;       // float4 index 0..4095
        int o = v >> 5;              // output row
        int i = (v & 31) << 2;       // input col
        float4 val = *reinterpret_cast<const float4*>(g + o * 128 + i);
        *reinterpret_cast<float4*>(sW + o * WS + i) = val;
    }
}

#define WCOMP(v, d) ((d) == 0 ? (v).x : (d) == 1 ? (v).y : (d) == 2 ? (v).z : (v).w)

// acc[8][8] = W(128x128) * H(128x128) restricted to this thread's 8x8 tile.
// sW is [o][WS] row-major; sH is [k][HS] row-major.
__device__ __forceinline__ void gemm_tile(const float* __restrict__ sW,
                                          const float* __restrict__ sH,
                                          int a0, int n0, float acc[8][8]) {
#pragma unroll
    for (int i = 0; i < 8; ++i)
#pragma unroll
        for (int j = 0; j < 8; ++j) acc[i][j] = 0.f;

#pragma unroll 2
    for (int kk = 0; kk < 128; kk += 4) {
        float4 w4[8];
#pragma unroll
        for (int i = 0; i < 8; ++i)
            w4[i] = *reinterpret_cast<const float4*>(sW + (a0 + i) * WS + kk);
        float4 hA[4], hB[4];
#pragma unroll
        for (int d = 0; d < 4; ++d) {
            hA[d] = *reinterpret_cast<const float4*>(sH + (kk + d) * HS + n0);
            hB[d] = *reinterpret_cast<const float4*>(sH + (kk + d) * HS + n0 + 4);
        }
#pragma unroll
        for (int d = 0; d < 4; ++d) {
            float hf[8] = {hA[d].x, hA[d].y, hA[d].z, hA[d].w,
                           hB[d].x, hB[d].y, hB[d].z, hB[d].w};
#pragma unroll
            for (int i = 0; i < 8; ++i) {
                float w = WCOMP(w4[i], d);
#pragma unroll
                for (int j = 0; j < 8; ++j)
                    acc[i][j] = fmaf(w, hf[j], acc[i][j]);
            }
        }
    }
}

// softplus(acc + bias) + eps, stored to out[(b*128+a)*16384 + t] as float4 pairs.
__device__ __forceinline__ void store_head(const float acc[8][8],
                                           const float* __restrict__ bias,
                                           float* __restrict__ outp,
                                           int a0, int n0, int b, int tbase) {
#pragma unroll
    for (int i = 0; i < 8; ++i) {
        float bv = __ldg(bias + a0 + i);
        float* go = outp + (((size_t)(b * 128 + a0 + i)) << 14) + tbase + n0;
        float4 o0, o1;
        o0.x = softplus_eps(acc[i][0] + bv);
        o0.y = softplus_eps(acc[i][1] + bv);
        o0.z = softplus_eps(acc[i][2] + bv);
        o0.w = softplus_eps(acc[i][3] + bv);
        o1.x = softplus_eps(acc[i][4] + bv);
        o1.y = softplus_eps(acc[i][5] + bv);
        o1.z = softplus_eps(acc[i][6] + bv);
        o1.w = softplus_eps(acc[i][7] + bv);
        *reinterpret_cast<float4*>(go)     = o0;
        *reinterpret_cast<float4*>(go + 4) = o1;
    }
}

__global__ void __launch_bounds__(256, 1)
ista_encoder_kernel(const float* __restrict__ x,  const float* __restrict__ Wx,
                    const float* __restrict__ bx, const float* __restrict__ Wh,
                    const float* __restrict__ Wk, const float* __restrict__ bk,
                    const float* __restrict__ Wt, const float* __restrict__ bt,
                    const float* __restrict__ Wp, const float* __restrict__ bp,
                    float* __restrict__ out) {
    extern __shared__ float smem[];
    float* sW  = smem;               // 128*132 floats, reused per stage
    float* sH  = smem + 128 * WS;    // 128 atoms x 128 tokens
    float* sHx = sH  + 128 * HS;     // conv output (iteration addend)

    const int tid   = threadIdx.x;
    const int tx    = tid & 15;
    const int a0    = (tid >> 4) * 8;   // this thread's 8 output rows (atoms)
    const int n0    = tx * 8;           // this thread's 8 token columns (local)
    const int blk   = blockIdx.x;       // 2048 blocks, 128 tokens each
    const int b     = blk >> 7;         // batch (Tp/128 = 128 blocks per batch)
    const int tbase = (blk & 127) << 7; // t offset within batch

    // ---------------- stage 0: h_x = Wx * x_blocks + bx ----------------
    // x is contiguous token-major: block's x data = x[blk*2048 .. +2048)
    float* sX  = sW;                  // [128 tokens][17] (padded)
    float* sWx = sW + 2176;           // [128][16] row-major
    float* sBx = sW + 2176 + 2048;    // [128]
    {
        const float4* gx4 = reinterpret_cast<const float4*>(x) + (size_t)blk * 512;
        float4 v0 = gx4[tid * 2];
        float4 v1 = gx4[tid * 2 + 1];
        float* dst = sX + (tid >> 1) * 17 + (tid & 1) * 8;
        dst[0] = v0.x; dst[1] = v0.y; dst[2] = v0.z; dst[3] = v0.w;
        dst[4] = v1.x; dst[5] = v1.y; dst[6] = v1.z; dst[7] = v1.w;
        const float4* gw4 = reinterpret_cast<const float4*>(Wx);
        reinterpret_cast<float4*>(sWx)[tid]       = gw4[tid];
        reinterpret_cast<float4*>(sWx)[tid + 256] = gw4[tid + 256];
        if (tid < 128) sBx[tid] = bx[tid];
    }
    __syncthreads();

    float acc[8][8];
#pragma unroll
    for (int i = 0; i < 8; ++i)
#pragma unroll
        for (int j = 0; j < 8; ++j) acc[i][j] = 0.f;
#pragma unroll
    for (int k = 0; k < 16; ++k) {
        float xf[8];
#pragma unroll
        for (int j = 0; j < 8; ++j) xf[j] = sX[(n0 + j) * 17 + k];
#pragma unroll
        for (int i = 0; i < 8; ++i) {
            float w = sWx[(a0 + i) * 16 + k];
#pragma unroll
            for (int j = 0; j < 8; ++j) acc[i][j] = fmaf(w, xf[j], acc[i][j]);
        }
    }
    // Hx = acc + bx;  iteration 1 of the scan is h = relu(Hx) (Wh @ 0 == 0)
#pragma unroll
    for (int i = 0; i < 8; ++i) {
        float bv = sBx[a0 + i];
        float* rowx = sHx + (a0 + i) * HS + n0;
        float* rowh = sH  + (a0 + i) * HS + n0;
#pragma unroll
        for (int j = 0; j < 8; ++j) {
            float v = acc[i][j] + bv;
            rowx[j] = v;
            rowh[j] = fmaxf(v, 0.f);
        }
    }
    __syncthreads();

    // ---------------- 7 remaining ReLU iterations: H = relu(Hx + Wh*H) --
    load_w128(Wh, sW, tid);
    __syncthreads();
    for (int it = 0; it < 7; ++it) {
        gemm_tile(sW, sH, a0, n0, acc);
        __syncthreads();   // all reads of sH complete before overwrite
#pragma unroll
        for (int i = 0; i < 8; ++i) {
            const float* rowx = sHx + (a0 + i) * HS + n0;
            float*       rowh = sH  + (a0 + i) * HS + n0;
            float4 x0 = *reinterpret_cast<const float4*>(rowx);
            float4 x1 = *reinterpret_cast<const float4*>(rowx + 4);
            float4 o0, o1;
            o0.x = fmaxf(x0.x + acc[i][0], 0.f);
            o0.y = fmaxf(x0.y + acc[i][1], 0.f);
            o0.z = fmaxf(x0.z + acc[i][2], 0.f);
            o0.w = fmaxf(x0.w + acc[i][3], 0.f);
            o1.x = fmaxf(x1.x + acc[i][4], 0.f);
            o1.y = fmaxf(x1.y + acc[i][5], 0.f);
            o1.z = fmaxf(x1.z + acc[i][6], 0.f);
            o1.w = fmaxf(x1.w + acc[i][7], 0.f);
            *reinterpret_cast<float4*>(rowh)     = o0;
            *reinterpret_cast<float4*>(rowh + 4) = o1;
        }
        __syncthreads();
    }

    const size_t OFF1 = (size_t)NBATCH * NATOM * TPRIME;  // 33554432 (k_out size)

    // ---------------- k head: softplus(Wk*h + bk) + eps -----------------
    load_w128(Wk, sW, tid);
    __syncthreads();
    gemm_tile(sW, sH, a0, n0, acc);
    store_head(acc, bk, out, a0, n0, b, tbase);
    __syncthreads();

    // ---------------- theta head: softplus(Wt*h + bt) + eps -------------
    load_w128(Wt, sW, tid);
    __syncthreads();
    gemm_tile(sW, sH, a0, n0, acc);
    store_head(acc, bt, out + OFF1, a0, n0, b, tbase);
    __syncthreads();

    // ---------------- logits: Wp*h + bp, layout [b,a,t,cls] -------------
    float* lout = out + 2 * OFF1;
    for (int c = 0; c < 3; ++c) {
        load_w128(Wp + c * 16384, sW, tid);
        __syncthreads();
        gemm_tile(sW, sH, a0, n0, acc);
#pragma unroll
        for (int i = 0; i < 8; ++i) {
            int o   = c * 128 + a0 + i;   // pi row = a*3 + cls
            int aa  = o / 3;
            int cls = o - aa * 3;
            float bv = __ldg(bp + o);
            float* go = lout +
                ((((size_t)(b * 128 + aa)) << 14) + tbase + n0) * 3 + cls;
#pragma unroll
            for (int j = 0; j < 8; ++j) go[3 * j] = acc[i][j] + bv;
        }
        __syncthreads();
    }
}

extern "C" void kernel_launch(void* const* d_in, const int* in_sizes, int n_in,
                              void* d_out, int out_size) {
    (void)in_sizes; (void)n_in; (void)out_size;
    const float* x  = (const float*)d_in[0];
    const float* Wx = (const float*)d_in[1];
    const float* bx = (const float*)d_in[2];
    const float* Wh = (const float*)d_in[3];
    const float* Wk = (const float*)d_in[4];
    const float* bk = (const float*)d_in[5];
    const float* Wt = (const float*)d_in[6];
    const float* bt = (const float*)d_in[7];
    const float* Wp = (const float*)d_in[8];
    const float* bp = (const float*)d_in[9];

    const size_t smem_bytes = (size_t)3 * 128 * 132 * sizeof(float);  // 202752 B
    cudaFuncSetAttribute(ista_encoder_kernel,
                         cudaFuncAttributeMaxDynamicSharedMemorySize,
                         (int)smem_bytes);
    ista_encoder_kernel<<<2048, 256, smem_bytes>>>(
        x, Wx, bx, Wh, Wk, bk, Wt, bt, Wp, bp, (float*)d_out);
}

// round 14
// speedup vs baseline: 1.0031x; 1.0031x over previous
#include <cuda_runtime.h>
#include <cstdint>

// Problem constants
#define NBATCH  16
#define NATOM   128
#define TPRIME  16384
#define WS      132     // padded row stride for weight tile in smem
#define HS      132     // padded row stride for H / Hx tiles in smem
#define EPSV    1e-4f

static __device__ __forceinline__ float softplus_eps(float v) {
    // jax.nn.softplus = logaddexp(v, 0) = max(v,0) + log1p(exp(-|v|))
    return fmaxf(v, 0.f) + log1pf(expf(-fabsf(v))) + EPSV;
}

// Load a 128x128 row-major fp32 matrix from gmem into smem [o][WS].
// Coalesced float4 gmem reads; smem float4 stores are conflict-free with WS=132.
__device__ __forceinline__ void load_w128(const float* __restrict__ g,
                                          float* __restrict__ sW, int tid) {
#pragma unroll
    for (int l = 0; l < 16; ++l) {
        int v = l * 256 + tid;       // float4 index 0..4095
        int o = v >> 5;              // output row
        int i = (v & 31) << 2;       // input col
        float4 val = *reinterpret_cast<const float4*>(g + o * 128 + i);
        *reinterpret_cast<float4*>(sW + o * WS + i) = val;
    }
}

#define WCOMP(v, d) ((d) == 0 ? (v).x : (d) == 1 ? (v).y : (d) == 2 ? (v).z : (v).w)

// acc[8][8] = W(128x128) * H(128x128) restricted to this thread's 8x8 tile.
// sW is [o][WS] row-major; sH is [k][HS] row-major.
__device__ __forceinline__ void gemm_tile(const float* __restrict__ sW,
                                          const float* __restrict__ sH,
                                          int a0, int n0, float acc[8][8]) {
#pragma unroll
    for (int i = 0; i < 8; ++i)
#pragma unroll
        for (int j = 0; j < 8; ++j) acc[i][j] = 0.f;

#pragma unroll 2
    for (int kk = 0; kk < 128; kk += 4) {
        float4 w4[8];
#pragma unroll
        for (int i = 0; i < 8; ++i)
            w4[i] = *reinterpret_cast<const float4*>(sW + (a0 + i) * WS + kk);
        float4 hA[4], hB[4];
#pragma unroll
        for (int d = 0; d < 4; ++d) {
            hA[d] = *reinterpret_cast<const float4*>(sH + (kk + d) * HS + n0);
            hB[d] = *reinterpret_cast<const float4*>(sH + (kk + d) * HS + n0 + 4);
        }
#pragma unroll
        for (int d = 0; d < 4; ++d) {
            float hf[8] = {hA[d].x, hA[d].y, hA[d].z, hA[d].w,
                           hB[d].x, hB[d].y, hB[d].z, hB[d].w};
#pragma unroll
            for (int i = 0; i < 8; ++i) {
                float w = WCOMP(w4[i], d);
#pragma unroll
                for (int j = 0; j < 8; ++j)
                    acc[i][j] = fmaf(w, hf[j], acc[i][j]);
            }
        }
    }
}

// softplus(acc + bias) + eps, stored to out[(b*128+a)*16384 + t] as float4 pairs.
__device__ __forceinline__ void store_head(const float acc[8][8],
                                           const float* __restrict__ bias,
                                           float* __restrict__ outp,
                                           int a0, int n0, int b, int tbase) {
#pragma unroll
    for (int i = 0; i < 8; ++i) {
        float bv = __ldg(bias + a0 + i);
        float* go = outp + (((size_t)(b * 128 + a0 + i)) << 14) + tbase + n0;
        float4 o0, o1;
        o0.x = softplus_eps(acc[i][0] + bv);
        o0.y = softplus_eps(acc[i][1] + bv);
        o0.z = softplus_eps(acc[i][2] + bv);
        o0.w = softplus_eps(acc[i][3] + bv);
        o1.x = softplus_eps(acc[i][4] + bv);
        o1.y = softplus_eps(acc[i][5] + bv);
        o1.z = softplus_eps(acc[i][6] + bv);
        o1.w = softplus_eps(acc[i][7] + bv);
        *reinterpret_cast<float4*>(go)     = o0;
        *reinterpret_cast<float4*>(go + 4) = o1;
    }
}

__global__ void __launch_bounds__(256, 1)
ista_encoder_kernel(const float* __restrict__ x,  const float* __restrict__ Wx,
                    const float* __restrict__ bx, const float* __restrict__ Wh,
                    const float* __restrict__ Wk, const float* __restrict__ bk,
                    const float* __restrict__ Wt, const float* __restrict__ bt,
                    const float* __restrict__ Wp, const float* __restrict__ bp,
                    float* __restrict__ out) {
    extern __shared__ float smem[];
    float* sW  = smem;               // 128*132 floats, reused per stage
    float* sH  = smem + 128 * WS;    // 128 atoms x 128 tokens
    float* sHx = sH  + 128 * HS;     // conv output (iteration addend)

    const int tid   = threadIdx.x;
    const int tx    = tid & 15;
    const int a0    = (tid >> 4) * 8;   // this thread's 8 output rows (atoms)
    const int n0    = tx * 8;           // this thread's 8 token columns (local)
    const int blk   = blockIdx.x;       // 2048 blocks, 128 tokens each
    const int b     = blk >> 7;         // batch (Tp/128 = 128 blocks per batch)
    const int tbase = (blk & 127) << 7; // t offset within batch

    // ---------------- stage 0: h_x = Wx * x_blocks + bx ----------------
    // x is contiguous token-major: block's x data = x[blk*2048 .. +2048)
    float* sX  = sW;                  // [128 tokens][17] (padded)
    float* sWx = sW + 2176;           // [128][16] row-major
    float* sBx = sW + 2176 + 2048;    // [128]
    {
        const float4* gx4 = reinterpret_cast<const float4*>(x) + (size_t)blk * 512;
        float4 v0 = gx4[tid * 2];
        float4 v1 = gx4[tid * 2 + 1];
        float* dst = sX + (tid >> 1) * 17 + (tid & 1) * 8;
        dst[0] = v0.x; dst[1] = v0.y; dst[2] = v0.z; dst[3] = v0.w;
        dst[4] = v1.x; dst[5] = v1.y; dst[6] = v1.z; dst[7] = v1.w;
        const float4* gw4 = reinterpret_cast<const float4*>(Wx);
        reinterpret_cast<float4*>(sWx)[tid]       = gw4[tid];
        reinterpret_cast<float4*>(sWx)[tid + 256] = gw4[tid + 256];
        if (tid < 128) sBx[tid] = bx[tid];
    }
    __syncthreads();

    float acc[8][8];
#pragma unroll
    for (int i = 0; i < 8; ++i)
#pragma unroll
        for (int j = 0; j < 8; ++j) acc[i][j] = 0.f;
#pragma unroll
    for (int k = 0; k < 16; ++k) {
        float xf[8];
#pragma unroll
        for (int j = 0; j < 8; ++j) xf[j] = sX[(n0 + j) * 17 + k];
#pragma unroll
        for (int i = 0; i < 8; ++i) {
            float w = sWx[(a0 + i) * 16 + k];
#pragma unroll
            for (int j = 0; j < 8; ++j) acc[i][j] = fmaf(w, xf[j], acc[i][j]);
        }
    }
    // Hx = acc + bx;  iteration 1 of the scan is h = relu(Hx) (Wh @ 0 == 0)
#pragma unroll
    for (int i = 0; i < 8; ++i) {
        float bv = sBx[a0 + i];
        float* rowx = sHx + (a0 + i) * HS + n0;
        float* rowh = sH  + (a0 + i) * HS + n0;
#pragma unroll
        for (int j = 0; j < 8; ++j) {
            float v = acc[i][j] + bv;
            rowx[j] = v;
            rowh[j] = fmaxf(v, 0.f);
        }
    }
    __syncthreads();

    // ---------------- 7 remaining ReLU iterations: H = relu(Hx + Wh*H) --
    load_w128(Wh, sW, tid);
    __syncthreads();
    for (int it = 0; it < 7; ++it) {
        gemm_tile(sW, sH, a0, n0, acc);
        __syncthreads();   // all reads of sH complete before overwrite
#pragma unroll
        for (int i = 0; i < 8; ++i) {
            const float* rowx = sHx + (a0 + i) * HS + n0;
            float*       rowh = sH  + (a0 + i) * HS + n0;
            float4 x0 = *reinterpret_cast<const float4*>(rowx);
            float4 x1 = *reinterpret_cast<const float4*>(rowx + 4);
            float4 o0, o1;
            o0.x = fmaxf(x0.x + acc[i][0], 0.f);
            o0.y = fmaxf(x0.y + acc[i][1], 0.f);
            o0.z = fmaxf(x0.z + acc[i][2], 0.f);
            o0.w = fmaxf(x0.w + acc[i][3], 0.f);
            o1.x = fmaxf(x1.x + acc[i][4], 0.f);
            o1.y = fmaxf(x1.y + acc[i][5], 0.f);
            o1.z = fmaxf(x1.z + acc[i][6], 0.f);
            o1.w = fmaxf(x1.w + acc[i][7], 0.f);
            *reinterpret_cast<float4*>(rowh)     = o0;
            *reinterpret_cast<float4*>(rowh + 4) = o1;
        }
        __syncthreads();
    }

    const size_t OFF1 = (size_t)NBATCH * NATOM * TPRIME;  // 33554432 (k_out size)

    // ---------------- k head: softplus(Wk*h + bk) + eps -----------------
    load_w128(Wk, sW, tid);
    __syncthreads();
    gemm_tile(sW, sH, a0, n0, acc);
    store_head(acc, bk, out, a0, n0, b, tbase);
    __syncthreads();

    // ---------------- theta head: softplus(Wt*h + bt) + eps -------------
    load_w128(Wt, sW, tid);
    __syncthreads();
    gemm_tile(sW, sH, a0, n0, acc);
    store_head(acc, bt, out + OFF1, a0, n0, b, tbase);
    __syncthreads();

    // ---------------- logits: Wp*h + bp, layout [b,a,t,cls] -------------
    float* lout = out + 2 * OFF1;
    for (int c = 0; c < 3; ++c) {
        load_w128(Wp + c * 16384, sW, tid);
        __syncthreads();
        gemm_tile(sW, sH, a0, n0, acc);
#pragma unroll
        for (int i = 0; i < 8; ++i) {
            int o   = c * 128 + a0 + i;   // pi row = a*3 + cls
            int aa  = o / 3;
            int cls = o - aa * 3;
            float bv = __ldg(bp + o);
            float* go = lout +
                ((((size_t)(b * 128 + aa)) << 14) + tbase + n0) * 3 + cls;
#pragma unroll
            for (int j = 0; j < 8; ++j) go[3 * j] = acc[i][j] + bv;
        }
        __syncthreads();
    }
}

extern "C" void kernel_launch(void* const* d_in, const int* in_sizes, int n_in,
                              void* d_out, int out_size) {
    (void)in_sizes; (void)n_in; (void)out_size;
    const float* x  = (const float*)d_in[0];
    const float* Wx = (const float*)d_in[1];
    const float* bx = (const float*)d_in[2];
    const float* Wh = (const float*)d_in[3];
    const float* Wk = (const float*)d_in[4];
    const float* bk = (const float*)d_in[5];
    const float* Wt = (const float*)d_in[6];
    const float* bt = (const float*)d_in[7];
    const float* Wp = (const float*)d_in[8];
    const float* bp = (const float*)d_in[9];

    const size_t smem_bytes = (size_t)3 * 128 * 132 * sizeof(float);  // 202752 B
    cudaFuncSetAttribute(ista_encoder_kernel,
                         cudaFuncAttributeMaxDynamicSharedMemorySize,
                         (int)smem_bytes);
    ista_encoder_kernel<<<2048, 256, smem_bytes>>>(
        x, Wx, bx, Wh, Wk, bk, Wt, bt, Wp, bp, (float*)d_out);
}